// round 3
// baseline (speedup 1.0000x reference)
#include <cuda_runtime.h>
#include <math.h>

// Problem constants: B=16, QL=VL=512, HID=1024, NH=4, DIM=256, CH=10
#define MBIAS 1
#define MKV   2
#define MCTX  3
#define MTANH 4
#define MFOLD 5

// ---------------- scratch (device globals; no allocations allowed) ----------
__device__ float dW2[768], dB2[256], dW2k[768], dW2v[768], dCk[1024], dCv[1024], dBq2[1024];
__device__ float dWq2[1024 * 1024], dWvk[1024 * 1024], dWvv[1024 * 1024];
__device__ float dQQ[8192 * 1024], dKK[8192 * 1024], dVV[8192 * 1024], dCTX[8192 * 1024];
__device__ float dATTN[64 * 512 * 512];   // fallback if d_out only holds `out`

// ---------------- tiny precompute kernels -----------------------------------
__global__ void prep1(const float* __restrict__ cw, const float* __restrict__ cb,
                      const float* __restrict__ Wloc) {
    int d = threadIdx.x;  // 256
    float w0 = 0.f, w1 = 0.f, w2 = 0.f, b2 = 0.f;
    for (int c = 0; c < 10; c++) {
        float wl = Wloc[c * 256 + d];
        w0 += cw[c * 3 + 0] * wl;
        w1 += cw[c * 3 + 1] * wl;
        w2 += cw[c * 3 + 2] * wl;
        b2 += cb[c] * wl;
    }
    dW2[d] = w0; dW2[256 + d] = w1; dW2[512 + d] = w2; dB2[d] = b2;
}

__global__ void prep2(const float* __restrict__ swq, const float* __restrict__ sbq,
                      const float* __restrict__ swk, const float* __restrict__ sbk,
                      const float* __restrict__ swv, const float* __restrict__ sbv,
                      const float* __restrict__ bias, const float* __restrict__ bq) {
    int idx = blockIdx.x * 256 + threadIdx.x;
    if (idx < 768) {                                   // W2k = W2 @ swk
        int k = idx >> 8, d = idx & 255; float s = 0.f;
        for (int e = 0; e < 256; e++) s += dW2[k * 256 + e] * swk[e * 256 + d];
        dW2k[idx] = s;
    } else if (idx < 1536) {                           // W2v = W2 @ swv
        int t = idx - 768; int k = t >> 8, d = t & 255; float s = 0.f;
        for (int e = 0; e < 256; e++) s += dW2[k * 256 + e] * swv[e * 256 + d];
        dW2v[t] = s;
    } else if (idx < 2560) {                           // ck[h,d]
        int t = idx - 1536; int h = t >> 8, d = t & 255; float s = sbk[d];
        for (int e = 0; e < 256; e++) s += (bias[h * 256 + e] + dB2[e]) * swk[e * 256 + d];
        dCk[t] = s;
    } else if (idx < 3584) {                           // cv[h,d]
        int t = idx - 2560; int h = t >> 8, d = t & 255; float s = sbv[d];
        for (int e = 0; e < 256; e++) s += (bias[h * 256 + e] + dB2[e]) * swv[e * 256 + d];
        dCv[t] = s;
    } else if (idx < 4608) {                           // bq2[c]
        int t = idx - 3584; int h = t >> 8, d = t & 255; float s = sbq[d];
        for (int e = 0; e < 256; e++) s += bq[h * 256 + e] * swq[e * 256 + d];
        dBq2[t] = s;
    }
}

// ---------------- generic 128x128x8 NN SGEMM with fused epilogues ----------
template <int MODE>
__global__ __launch_bounds__(256, 2)
void gemm128(const float* __restrict__ A, const float* __restrict__ A2,
             const float* __restrict__ Bm, float* __restrict__ C,
             int K, int lda, int ldb, int ldc,
             const float* __restrict__ bias,
             const float* __restrict__ pa,
             const float* __restrict__ W2x,
             const float* __restrict__ cx) {
    int z = blockIdx.z;
    if (MODE == MFOLD) { A += z * 256; C += z * 256; }
    if (MODE == MCTX) {
        int b = z & 15, h = z >> 4;                 // n = h*16 + b
        A  += (size_t)z * (512 * 512);
        Bm += (size_t)b * (512 * 1024) + h * 256;
        C  += (size_t)b * (512 * 1024) + h * 256;
    }
    __shared__ float As[8][132];
    __shared__ float Bs[8][128];
    int tid = threadIdx.x;
    int tx = tid & 15, ty = tid >> 4;
    int bm = blockIdx.y * 128, bn = blockIdx.x * 128;

    float acc[8][8];
#pragma unroll
    for (int i = 0; i < 8; i++)
#pragma unroll
        for (int j = 0; j < 8; j++) acc[i][j] = 0.f;

    int arow = tid >> 1;
    int ak4  = (tid & 1) * 4;
    int brow = tid >> 5;
    int bc4  = (tid & 31) * 4;

    for (int k0 = 0; k0 < K; k0 += 8) {
        const float* Asrc = A; int kb = k0;
        if (MODE == MTANH && k0 >= 1024) { Asrc = A2; kb = k0 - 1024; }
        float4 av = *(const float4*)&Asrc[(size_t)(bm + arow) * lda + kb + ak4];
        As[ak4 + 0][arow] = av.x; As[ak4 + 1][arow] = av.y;
        As[ak4 + 2][arow] = av.z; As[ak4 + 3][arow] = av.w;
        float4 bv = *(const float4*)&Bm[(size_t)(k0 + brow) * ldb + bn + bc4];
        *(float4*)&Bs[brow][bc4] = bv;
        __syncthreads();
#pragma unroll
        for (int kk = 0; kk < 8; kk++) {
            float a[8], b[8];
            float4 t0 = *(const float4*)&As[kk][ty * 4];
            float4 t1 = *(const float4*)&As[kk][64 + ty * 4];
            float4 u0 = *(const float4*)&Bs[kk][tx * 4];
            float4 u1 = *(const float4*)&Bs[kk][64 + tx * 4];
            a[0] = t0.x; a[1] = t0.y; a[2] = t0.z; a[3] = t0.w;
            a[4] = t1.x; a[5] = t1.y; a[6] = t1.z; a[7] = t1.w;
            b[0] = u0.x; b[1] = u0.y; b[2] = u0.z; b[3] = u0.w;
            b[4] = u1.x; b[5] = u1.y; b[6] = u1.z; b[7] = u1.w;
#pragma unroll
            for (int i = 0; i < 8; i++)
#pragma unroll
                for (int j = 0; j < 8; j++) acc[i][j] = fmaf(a[i], b[j], acc[i][j]);
        }
        __syncthreads();
    }

    int h_kv = blockIdx.x >> 1;   // 128-col tile lies inside one 256-wide head block
#pragma unroll
    for (int i = 0; i < 8; i++) {
        int r = bm + ((i < 4) ? ty * 4 + i : 64 + ty * 4 + i - 4);
        float p0 = 0.f, p1 = 0.f, p2 = 0.f;
        if (MODE == MKV) {
            int l = r & 511;
            size_t base = (size_t)(((r >> 9) << 2) + h_kv) * 512;  // pa row = b*4 + h
            p0 = (l >= 1)   ? pa[base + l - 1] : 0.f;
            p1 =              pa[base + l];
            p2 = (l <= 510) ? pa[base + l + 1] : 0.f;
        }
#pragma unroll
        for (int j = 0; j < 8; j++) {
            int c = bn + ((j < 4) ? tx * 4 + j : 64 + tx * 4 + j - 4);
            float v = acc[i][j];
            if (MODE == MBIAS) v += bias[c];
            if (MODE == MKV) {
                int d = c & 255;
                v += cx[c] + p0 * W2x[d] + p1 * W2x[256 + d] + p2 * W2x[512 + d];
            }
            if (MODE == MTANH) v = tanhf(v + bias[c]);
            C[(size_t)r * ldc + c] = v;
        }
    }
}

// ---------------- scores: NT GEMM, per-(h,b), writes attn (pre-softmax) -----
__global__ __launch_bounds__(256, 2)
void gemmScores(const float* __restrict__ qq, const float* __restrict__ kk,
                float* __restrict__ attn) {
    int z = blockIdx.z; int h = z >> 4, b = z & 15;
    const float* A  = qq + (size_t)b * (512 * 1024) + h * 256;
    const float* Bm = kk + (size_t)b * (512 * 1024) + h * 256;
    float* C = attn + (size_t)z * (512 * 512);
    __shared__ float As[8][132];
    __shared__ float Bs[8][132];
    int tid = threadIdx.x, tx = tid & 15, ty = tid >> 4;
    int bm = blockIdx.y * 128, bn = blockIdx.x * 128;
    float acc[8][8];
#pragma unroll
    for (int i = 0; i < 8; i++)
#pragma unroll
        for (int j = 0; j < 8; j++) acc[i][j] = 0.f;
    int arow = tid >> 1, ak4 = (tid & 1) * 4;
    for (int k0 = 0; k0 < 256; k0 += 8) {
        float4 av = *(const float4*)&A[(size_t)(bm + arow) * 1024 + k0 + ak4];
        As[ak4 + 0][arow] = av.x; As[ak4 + 1][arow] = av.y;
        As[ak4 + 2][arow] = av.z; As[ak4 + 3][arow] = av.w;
        float4 bv = *(const float4*)&Bm[(size_t)(bn + arow) * 1024 + k0 + ak4];
        Bs[ak4 + 0][arow] = bv.x; Bs[ak4 + 1][arow] = bv.y;
        Bs[ak4 + 2][arow] = bv.z; Bs[ak4 + 3][arow] = bv.w;
        __syncthreads();
#pragma unroll
        for (int kk2 = 0; kk2 < 8; kk2++) {
            float a[8], b2[8];
            float4 t0 = *(const float4*)&As[kk2][ty * 4];
            float4 t1 = *(const float4*)&As[kk2][64 + ty * 4];
            float4 u0 = *(const float4*)&Bs[kk2][tx * 4];
            float4 u1 = *(const float4*)&Bs[kk2][64 + tx * 4];
            a[0] = t0.x; a[1] = t0.y; a[2] = t0.z; a[3] = t0.w;
            a[4] = t1.x; a[5] = t1.y; a[6] = t1.z; a[7] = t1.w;
            b2[0] = u0.x; b2[1] = u0.y; b2[2] = u0.z; b2[3] = u0.w;
            b2[4] = u1.x; b2[5] = u1.y; b2[6] = u1.z; b2[7] = u1.w;
#pragma unroll
            for (int i = 0; i < 8; i++)
#pragma unroll
                for (int j = 0; j < 8; j++) acc[i][j] = fmaf(a[i], b2[j], acc[i][j]);
        }
        __syncthreads();
    }
#pragma unroll
    for (int i = 0; i < 8; i++) {
        int r = bm + ((i < 4) ? ty * 4 + i : 64 + ty * 4 + i - 4);
#pragma unroll
        for (int j = 0; j < 8; j++) {
            int c = bn + ((j < 4) ? tx * 4 + j : 64 + tx * 4 + j - 4);
            C[(size_t)r * 512 + c] = acc[i][j] * 0.0625f;   // 1/sqrt(256)
        }
    }
}

// ---------------- row softmax over 512 elements ------------------------------
__global__ void softmax512(float* __restrict__ a) {
    float* p = a + (size_t)blockIdx.x * 512;
    int t = threadIdx.x;               // 128 threads
    float4 v = *(float4*)&p[t * 4];
    float m = fmaxf(fmaxf(v.x, v.y), fmaxf(v.z, v.w));
#pragma unroll
    for (int o = 16; o > 0; o >>= 1) m = fmaxf(m, __shfl_xor_sync(0xffffffffu, m, o));
    __shared__ float sh[4], sh2[4];
    int w = t >> 5, lane = t & 31;
    if (lane == 0) sh[w] = m;
    __syncthreads();
    m = fmaxf(fmaxf(sh[0], sh[1]), fmaxf(sh[2], sh[3]));
    v.x = __expf(v.x - m); v.y = __expf(v.y - m);
    v.z = __expf(v.z - m); v.w = __expf(v.w - m);
    float s = v.x + v.y + v.z + v.w;
#pragma unroll
    for (int o = 16; o > 0; o >>= 1) s += __shfl_xor_sync(0xffffffffu, s, o);
    if (lane == 0) sh2[w] = s;
    __syncthreads();
    s = sh2[0] + sh2[1] + sh2[2] + sh2[3];
    float inv = 1.f / s;
    v.x *= inv; v.y *= inv; v.z *= inv; v.w *= inv;
    *(float4*)&p[t * 4] = v;
}

// ---------------- launch ------------------------------------------------------
extern "C" void kernel_launch(void* const* d_in, const int* in_sizes, int n_in,
                              void* d_out, int out_size) {
    const float* query = (const float*)d_in[0];
    const float* value = (const float*)d_in[1];
    const float* pa    = (const float*)d_in[2];
    const float* cw    = (const float*)d_in[3];
    const float* cb    = (const float*)d_in[4];
    const float* Wq    = (const float*)d_in[5];
    const float* bq    = (const float*)d_in[6];
    const float* Wv    = (const float*)d_in[7];
    const float* Wloc  = (const float*)d_in[8];
    const float* bias  = (const float*)d_in[9];
    const float* Wout  = (const float*)d_in[10];
    const float* bout  = (const float*)d_in[11];
    const float* swq   = (const float*)d_in[12];
    const float* sbq   = (const float*)d_in[13];
    const float* swk   = (const float*)d_in[14];
    const float* sbk   = (const float*)d_in[15];
    const float* swv   = (const float*)d_in[16];
    const float* sbv   = (const float*)d_in[17];

    float* out = (float*)d_out;
    const size_t OUT_ELEMS  = (size_t)16 * 512 * 1024;        // 8,388,608
    const size_t ATTN_ELEMS = (size_t)64 * 512 * 512;         // 16,777,216

    float *pWq2, *pWvk, *pWvv, *pQQ, *pKK, *pVV, *pCTX, *pW2k, *pW2v, *pCk, *pCv, *pBq2, *pATT;
    cudaGetSymbolAddress((void**)&pWq2, dWq2);
    cudaGetSymbolAddress((void**)&pWvk, dWvk);
    cudaGetSymbolAddress((void**)&pWvv, dWvv);
    cudaGetSymbolAddress((void**)&pQQ, dQQ);
    cudaGetSymbolAddress((void**)&pKK, dKK);
    cudaGetSymbolAddress((void**)&pVV, dVV);
    cudaGetSymbolAddress((void**)&pCTX, dCTX);
    cudaGetSymbolAddress((void**)&pW2k, dW2k);
    cudaGetSymbolAddress((void**)&pW2v, dW2v);
    cudaGetSymbolAddress((void**)&pCk, dCk);
    cudaGetSymbolAddress((void**)&pCv, dCv);
    cudaGetSymbolAddress((void**)&pBq2, dBq2);
    cudaGetSymbolAddress((void**)&pATT, dATTN);

    // attn goes straight into d_out if the harness expects (out, attn) concatenated
    float* attn = ((size_t)out_size >= OUT_ELEMS + ATTN_ELEMS) ? (out + OUT_ELEMS) : pATT;

    dim3 T(256);
    prep1<<<1, 256>>>(cw, cb, Wloc);
    prep2<<<18, 256>>>(swq, sbq, swk, sbk, swv, sbv, bias, bq);

    // weight folds: Wq2 = Wq*blockdiag(swq), Wvk = Wv*blockdiag(swk), Wvv = Wv*blockdiag(swv)
    gemm128<MFOLD><<<dim3(2, 8, 4), T>>>(Wq, nullptr, swq, pWq2, 256, 1024, 256, 1024,
                                         nullptr, nullptr, nullptr, nullptr);
    gemm128<MFOLD><<<dim3(2, 8, 4), T>>>(Wv, nullptr, swk, pWvk, 256, 1024, 256, 1024,
                                         nullptr, nullptr, nullptr, nullptr);
    gemm128<MFOLD><<<dim3(2, 8, 4), T>>>(Wv, nullptr, swv, pWvv, 256, 1024, 256, 1024,
                                         nullptr, nullptr, nullptr, nullptr);

    // qq / kk / vv (8192 x 1024 x 1024 each), loc + biases fused into epilogues
    gemm128<MBIAS><<<dim3(8, 64, 1), T>>>(query, nullptr, pWq2, pQQ, 1024, 1024, 1024, 1024,
                                          pBq2, nullptr, nullptr, nullptr);
    gemm128<MKV><<<dim3(8, 64, 1), T>>>(value, nullptr, pWvk, pKK, 1024, 1024, 1024, 1024,
                                        nullptr, pa, pW2k, pCk);
    gemm128<MKV><<<dim3(8, 64, 1), T>>>(value, nullptr, pWvv, pVV, 1024, 1024, 1024, 1024,
                                        nullptr, pa, pW2v, pCv);

    // attention
    gemmScores<<<dim3(4, 4, 64), T>>>(pQQ, pKK, attn);
    softmax512<<<64 * 512, 128>>>(attn);
    gemm128<MCTX><<<dim3(2, 4, 64), T>>>(attn, nullptr, pVV, pCTX, 512, 512, 1024, 1024,
                                         nullptr, nullptr, nullptr, nullptr);

    // out = tanh([ctx, query] @ Wout + bout)
    gemm128<MTANH><<<dim3(8, 64, 1), T>>>(pCTX, query, Wout, out, 2048, 1024, 1024, 1024,
                                          bout, nullptr, nullptr, nullptr);
}

// round 7
// speedup vs baseline: 1.8110x; 1.8110x over previous
#include <cuda_runtime.h>
#include <cuda_bf16.h>
#include <math.h>
#include <stdint.h>

typedef __nv_bfloat16 BF;

// Problem constants: B=16, QL=VL=512, HID=1024, NH=4, DIM=256, CH=10
#define SZ_ACT (8192 * 1024)
#define SZ_ATT (64 * 512 * 512)

// GEMM modes
#define TFOLD 0
#define TQQ   1
#define TKK   2
#define TVV   3
#define TSC   4
#define TCTX  5
#define TTANH 6

// ------------------------- device scratch ------------------------------------
__device__ float dW2[768], dB2[256], dW2k[768], dW2v[768], dCk[1024], dCv[1024], dBq2[1024];
__device__ float dATTN[SZ_ATT];

__device__ __align__(256) BF g_qhi[SZ_ACT],   g_qlo[SZ_ACT];
__device__ __align__(256) BF g_vhi[SZ_ACT],   g_vlo[SZ_ACT];
__device__ __align__(256) BF g_Wqhi[1048576], g_Wqlo[1048576];
__device__ __align__(256) BF g_Wvhi[1048576], g_Wvlo[1048576];
__device__ __align__(256) BF g_sqThi[65536],  g_sqTlo[65536];
__device__ __align__(256) BF g_skThi[65536],  g_skTlo[65536];
__device__ __align__(256) BF g_svThi[65536],  g_svTlo[65536];
__device__ __align__(256) BF g_WoThi[2097152], g_WoTlo[2097152];
__device__ __align__(256) BF g_Wq2Thi[1048576], g_Wq2Tlo[1048576];
__device__ __align__(256) BF g_WvkThi[1048576], g_WvkTlo[1048576];
__device__ __align__(256) BF g_WvvThi[1048576], g_WvvTlo[1048576];
__device__ __align__(256) BF g_qqhi[SZ_ACT],  g_qqlo[SZ_ACT];
__device__ __align__(256) BF g_kkhi[SZ_ACT],  g_kklo[SZ_ACT];
__device__ __align__(256) BF g_vvhi[SZ_ACT],  g_vvlo[SZ_ACT];
__device__ __align__(256) BF g_vvThi[SZ_ACT], g_vvTlo[SZ_ACT];
__device__ __align__(256) BF g_athi[SZ_ATT],  g_atlo[SZ_ATT];
__device__ __align__(256) BF g_cxhi[SZ_ACT],  g_cxlo[SZ_ACT];

// ------------------------- helpers -------------------------------------------
__device__ __forceinline__ uint32_t smem_u32(const void* p) {
    uint32_t a;
    asm("{ .reg .u64 t; cvta.to.shared.u64 t, %1; cvt.u32.u64 %0, t; }" : "=r"(a) : "l"(p));
    return a;
}
__device__ __forceinline__ unsigned short sp(float v, unsigned short* lo) {
    BF h = __float2bfloat16(v);
    BF l = __float2bfloat16(v - __bfloat162float(h));
    *lo = __bfloat16_as_ushort(l);
    return __bfloat16_as_ushort(h);
}

#define LDSM4(r0, r1, r2, r3, a) \
    asm volatile("ldmatrix.sync.aligned.m8n8.x4.shared.b16 {%0,%1,%2,%3}, [%4];" \
        : "=r"(r0), "=r"(r1), "=r"(r2), "=r"(r3) : "r"(a))
#define LDSM2(r0, r1, a) \
    asm volatile("ldmatrix.sync.aligned.m8n8.x2.shared.b16 {%0,%1}, [%2];" \
        : "=r"(r0), "=r"(r1) : "r"(a))
#define MMA16816(c, a, b) \
    asm volatile("mma.sync.aligned.m16n8k16.row.col.f32.bf16.bf16.f32 " \
        "{%0,%1,%2,%3}, {%4,%5,%6,%7}, {%8,%9}, {%0,%1,%2,%3};" \
        : "+f"((c)[0]), "+f"((c)[1]), "+f"((c)[2]), "+f"((c)[3]) \
        : "r"((a)[0]), "r"((a)[1]), "r"((a)[2]), "r"((a)[3]), "r"((b)[0]), "r"((b)[1]))

// ------------------------- tiny precompute -----------------------------------
__global__ void prep1(const float* __restrict__ cw, const float* __restrict__ cb,
                      const float* __restrict__ Wloc) {
    int d = threadIdx.x;  // 256
    float w0 = 0.f, w1 = 0.f, w2 = 0.f, b2 = 0.f;
    for (int c = 0; c < 10; c++) {
        float wl = Wloc[c * 256 + d];
        w0 += cw[c * 3 + 0] * wl; w1 += cw[c * 3 + 1] * wl; w2 += cw[c * 3 + 2] * wl;
        b2 += cb[c] * wl;
    }
    dW2[d] = w0; dW2[256 + d] = w1; dW2[512 + d] = w2; dB2[d] = b2;
}

__global__ void prep2(const float* __restrict__ swq, const float* __restrict__ sbq,
                      const float* __restrict__ swk, const float* __restrict__ sbk,
                      const float* __restrict__ swv, const float* __restrict__ sbv,
                      const float* __restrict__ bias, const float* __restrict__ bq) {
    int idx = blockIdx.x * 256 + threadIdx.x;
    if (idx < 768) {
        int k = idx >> 8, d = idx & 255; float s = 0.f;
        for (int e = 0; e < 256; e++) s += dW2[k * 256 + e] * swk[e * 256 + d];
        dW2k[idx] = s;
    } else if (idx < 1536) {
        int t = idx - 768; int k = t >> 8, d = t & 255; float s = 0.f;
        for (int e = 0; e < 256; e++) s += dW2[k * 256 + e] * swv[e * 256 + d];
        dW2v[t] = s;
    } else if (idx < 2560) {
        int t = idx - 1536; int h = t >> 8, d = t & 255; float s = sbk[d];
        for (int e = 0; e < 256; e++) s += (bias[h * 256 + e] + dB2[e]) * swk[e * 256 + d];
        dCk[t] = s;
    } else if (idx < 3584) {
        int t = idx - 2560; int h = t >> 8, d = t & 255; float s = sbv[d];
        for (int e = 0; e < 256; e++) s += (bias[h * 256 + e] + dB2[e]) * swv[e * 256 + d];
        dCv[t] = s;
    } else if (idx < 4608) {
        int t = idx - 3584; int h = t >> 8, d = t & 255; float s = sbq[d];
        for (int e = 0; e < 256; e++) s += bq[h * 256 + e] * swq[e * 256 + d];
        dBq2[t] = s;
    }
}

// ------------------------- split / transpose ---------------------------------
__global__ void splitKn(const float4* __restrict__ s, ushort4* __restrict__ hi,
                        ushort4* __restrict__ lo, int n4) {
    int i = blockIdx.x * 256 + threadIdx.x;
    if (i >= n4) return;
    float4 v = s[i]; ushort4 h, l;
    h.x = sp(v.x, &l.x); h.y = sp(v.y, &l.y); h.z = sp(v.z, &l.z); h.w = sp(v.w, &l.w);
    hi[i] = h; lo[i] = l;
}

// out[c][r] = src[r][c]; src R x C row-major, out C x R
__global__ void splitT(const float* __restrict__ s, unsigned short* __restrict__ hi,
                       unsigned short* __restrict__ lo, int R, int C) {
    __shared__ float t[32][33];
    int r0 = blockIdx.y * 32, c0 = blockIdx.x * 32;
    int tx = threadIdx.x & 31, ty = threadIdx.x >> 5;
    for (int y = ty; y < 32; y += 8) t[y][tx] = s[(size_t)(r0 + y) * C + c0 + tx];
    __syncthreads();
    for (int y = ty; y < 32; y += 8) {
        unsigned short l_;
        unsigned short h_ = sp(t[tx][y], &l_);
        size_t o = (size_t)(c0 + y) * R + r0 + tx;
        hi[o] = h_; lo[o] = l_;
    }
}

// vv [(b*512+l)*1024 + h*256+d] -> vvT [((h*16+b)*256+d)*512 + l]
__global__ void transVV(const unsigned short* __restrict__ shi, const unsigned short* __restrict__ slo,
                        unsigned short* __restrict__ thi, unsigned short* __restrict__ tlo) {
    __shared__ unsigned short t0[32][33], t1[32][33];
    int l0 = blockIdx.x * 32, d0 = blockIdx.y * 32;
    int z = blockIdx.z, h = z >> 4, b = z & 15;
    int tx = threadIdx.x & 31, ty = threadIdx.x >> 5;
    for (int y = ty; y < 32; y += 8) {
        size_t s = (size_t)(b * 512 + l0 + y) * 1024 + h * 256 + d0 + tx;
        t0[y][tx] = shi[s]; t1[y][tx] = slo[s];
    }
    __syncthreads();
    for (int y = ty; y < 32; y += 8) {
        size_t o = (size_t)(z * 256 + d0 + y) * 512 + l0 + tx;
        thi[o] = t0[tx][y]; tlo[o] = t1[tx][y];
    }
}

// ------------------------- softmax row-512 + split emit ----------------------
__global__ void softmax512(float* __restrict__ a, ushort4* __restrict__ hi, ushort4* __restrict__ lo) {
    float* p = a + (size_t)blockIdx.x * 512;
    int t = threadIdx.x;  // 128
    float4 v = *(float4*)&p[t * 4];
    float m = fmaxf(fmaxf(v.x, v.y), fmaxf(v.z, v.w));
#pragma unroll
    for (int o = 16; o > 0; o >>= 1) m = fmaxf(m, __shfl_xor_sync(0xffffffffu, m, o));
    __shared__ float sh[4], sh2[4];
    int w = t >> 5, lane = t & 31;
    if (lane == 0) sh[w] = m;
    __syncthreads();
    m = fmaxf(fmaxf(sh[0], sh[1]), fmaxf(sh[2], sh[3]));
    v.x = __expf(v.x - m); v.y = __expf(v.y - m); v.z = __expf(v.z - m); v.w = __expf(v.w - m);
    float s = v.x + v.y + v.z + v.w;
#pragma unroll
    for (int o = 16; o > 0; o >>= 1) s += __shfl_xor_sync(0xffffffffu, s, o);
    if (lane == 0) sh2[w] = s;
    __syncthreads();
    s = sh2[0] + sh2[1] + sh2[2] + sh2[3];
    float inv = 1.f / s;
    v.x *= inv; v.y *= inv; v.z *= inv; v.w *= inv;
    *(float4*)&p[t * 4] = v;
    ushort4 h4, l4;
    h4.x = sp(v.x, &l4.x); h4.y = sp(v.y, &l4.y); h4.z = sp(v.z, &l4.z); h4.w = sp(v.w, &l4.w);
    hi[(size_t)blockIdx.x * 128 + t] = h4;
    lo[(size_t)blockIdx.x * 128 + t] = l4;
}

// ------------------------- mma.sync split-precision GEMM ---------------------
// D[m,n] = sum_k A[m,k]*B[n,k]; 3 bf16 passes: AhiBhi + AloBhi + AhiBlo.
// Block tile 128x128, 8 warps (2x4), warp tile 64x32. K-chunks of 32 halves,
// SMEM rows padded to 40 halves (80B) -> conflict-free ldmatrix.
template <int MODE>
__global__ __launch_bounds__(256, 2)
void gemmTC(const BF* __restrict__ Ahi, const BF* __restrict__ Alo,
            const BF* __restrict__ A2hi, const BF* __restrict__ A2lo,
            const BF* __restrict__ Bhi, const BF* __restrict__ Blo,
            BF* __restrict__ Chi, BF* __restrict__ Clo, float* __restrict__ Cf,
            int K, int lda, int ldb, int ldc,
            const float* __restrict__ bias, const float* __restrict__ pa,
            const float* __restrict__ W2x, const float* __restrict__ cx) {
    __shared__ BF As[2][128 * 40];
    __shared__ BF Bs[2][128 * 40];

    const int tid = threadIdx.x;
    const int lane = tid & 31, wid = tid >> 5;
    const int wm = (wid >> 2) * 64, wn = (wid & 3) * 32;
    const int bm = blockIdx.y * 128, bn = blockIdx.x * 128;
    const int z = blockIdx.z;

    if (MODE == TFOLD) {
        Bhi += z * 256; Blo += z * 256;
        Chi += (size_t)z * 256 * ldc; Clo += (size_t)z * 256 * ldc;
    }
    if (MODE == TSC) {
        int h = z >> 4, b = z & 15;
        size_t o = (size_t)b * 512 * 1024 + h * 256;
        Ahi += o; Alo += o; Bhi += o; Blo += o;
        Cf += (size_t)z * 262144;
    }
    if (MODE == TCTX) {
        int h = z >> 4, b = z & 15;
        size_t oa = (size_t)z * 262144; Ahi += oa; Alo += oa;
        size_t ob = (size_t)z * 131072; Bhi += ob; Blo += ob;
        size_t oc = (size_t)b * 512 * 1024 + h * 256; Chi += oc; Clo += oc;
    }

    float acc[4][4][4];
#pragma unroll
    for (int a = 0; a < 4; a++)
#pragma unroll
        for (int b = 0; b < 4; b++)
#pragma unroll
            for (int c = 0; c < 4; c++) acc[a][b][c] = 0.f;

    const int KCseg = K >> 5;
    const int NCH = 3 * KCseg;

    const int rowA = tid >> 2;          // 0..63
    const int segA = (tid & 3) * 8;     // half offset within 32-half row

    uint32_t aB0 = smem_u32(As[0]), aB1 = smem_u32(As[1]);
    uint32_t bB0 = smem_u32(Bs[0]), bB1 = smem_u32(Bs[1]);

    uint4 ra0, ra1, rb0, rb1;
    int k0a;

#define LOADCH(cc_) do {                                                          \
    int sgm = (cc_) / KCseg;                                                      \
    int k0 = ((cc_) - sgm * KCseg) << 5;                                          \
    const BF* Ap = (sgm == 1) ? Alo : Ahi;                                        \
    const BF* Bp = (sgm == 2) ? Blo : Bhi;                                        \
    k0a = k0;                                                                     \
    if (MODE == TTANH && k0 >= 1024) { Ap = (sgm == 1) ? A2lo : A2hi; k0a = k0 - 1024; } \
    ra0 = *(const uint4*)(Ap + (size_t)(bm + rowA) * lda + k0a + segA);           \
    ra1 = *(const uint4*)(Ap + (size_t)(bm + rowA + 64) * lda + k0a + segA);      \
    rb0 = *(const uint4*)(Bp + (size_t)(bn + rowA) * ldb + k0 + segA);            \
    rb1 = *(const uint4*)(Bp + (size_t)(bn + rowA + 64) * ldb + k0 + segA);       \
} while (0)

#define STORECH(buf_) do {                                                        \
    *(uint4*)&As[buf_][rowA * 40 + segA] = ra0;                                   \
    *(uint4*)&As[buf_][(rowA + 64) * 40 + segA] = ra1;                            \
    *(uint4*)&Bs[buf_][rowA * 40 + segA] = rb0;                                   \
    *(uint4*)&Bs[buf_][(rowA + 64) * 40 + segA] = rb1;                            \
} while (0)

    LOADCH(0);
    STORECH(0);
    __syncthreads();

    const int la15 = lane & 15;
    const int laHi = (lane >> 4) << 3;
    const int tt = lane & 15;
    const int ttr = tt & 7, ttk = (tt >> 3) << 3;

    for (int c = 0; c < NCH; c++) {
        int buf = c & 1;
        if (c + 1 < NCH) LOADCH(c + 1);
        uint32_t aBase = buf ? aB1 : aB0;
        uint32_t bBase = buf ? bB1 : bB0;
#pragma unroll
        for (int kk = 0; kk < 2; kk++) {
            uint32_t af[4][4], bf_[4][2];
#pragma unroll
            for (int mt = 0; mt < 4; mt++) {
                uint32_t addr = aBase + ((wm + mt * 16 + la15) * 40 + kk * 16 + laHi) * 2;
                LDSM4(af[mt][0], af[mt][1], af[mt][2], af[mt][3], addr);
            }
#pragma unroll
            for (int nt = 0; nt < 4; nt++) {
                uint32_t addr = bBase + ((wn + nt * 8 + ttr) * 40 + kk * 16 + ttk) * 2;
                LDSM2(bf_[nt][0], bf_[nt][1], addr);
            }
#pragma unroll
            for (int mt = 0; mt < 4; mt++)
#pragma unroll
                for (int nt = 0; nt < 4; nt++)
                    MMA16816(acc[mt][nt], af[mt], bf_[nt]);
        }
        __syncthreads();
        if (c + 1 < NCH) { STORECH(buf ^ 1); __syncthreads(); }
    }

    // ------------- epilogue: fused math + hi/lo emit, straight from regs -----
#pragma unroll
    for (int mt = 0; mt < 4; mt++) {
        int r0g = bm + wm + mt * 16 + (lane >> 2);
        int r1g = r0g + 8;
        float p0a = 0.f, p1a = 0.f, p2a = 0.f, p0b = 0.f, p1b = 0.f, p2b = 0.f;
        if (MODE == TKK || MODE == TVV) {
            int hh = (bn + wn) >> 8;
            {
                int b = r0g >> 9, l = r0g & 511;
                size_t pb = (size_t)(b * 4 + hh) * 512;
                p0a = (l >= 1)   ? pa[pb + l - 1] : 0.f;
                p1a =              pa[pb + l];
                p2a = (l <= 510) ? pa[pb + l + 1] : 0.f;
            }
            {
                int b = r1g >> 9, l = r1g & 511;
                size_t pb = (size_t)(b * 4 + hh) * 512;
                p0b = (l >= 1)   ? pa[pb + l - 1] : 0.f;
                p1b =              pa[pb + l];
                p2b = (l <= 510) ? pa[pb + l + 1] : 0.f;
            }
        }
#pragma unroll
        for (int nt = 0; nt < 4; nt++) {
            int cc = bn + wn + nt * 8 + (lane & 3) * 2;
            float v00 = acc[mt][nt][0], v01 = acc[mt][nt][1];
            float v10 = acc[mt][nt][2], v11 = acc[mt][nt][3];
            if (MODE == TQQ) {
                float b0 = bias[cc], b1 = bias[cc + 1];
                v00 += b0; v01 += b1; v10 += b0; v11 += b1;
            }
            if (MODE == TKK || MODE == TVV) {
                int d0 = cc & 255, d1 = d0 + 1;
                float c0 = cx[cc], c1 = cx[cc + 1];
                float w00 = W2x[d0], w10 = W2x[256 + d0], w20 = W2x[512 + d0];
                float w01 = W2x[d1], w11 = W2x[256 + d1], w21 = W2x[512 + d1];
                v00 += c0 + p0a * w00 + p1a * w10 + p2a * w20;
                v01 += c1 + p0a * w01 + p1a * w11 + p2a * w21;
                v10 += c0 + p0b * w00 + p1b * w10 + p2b * w20;
                v11 += c1 + p0b * w01 + p1b * w11 + p2b * w21;
            }
            if (MODE == TSC) { v00 *= 0.0625f; v01 *= 0.0625f; v10 *= 0.0625f; v11 *= 0.0625f; }
            if (MODE == TTANH) {
                float b0 = bias[cc], b1 = bias[cc + 1];
                v00 = tanhf(v00 + b0); v01 = tanhf(v01 + b1);
                v10 = tanhf(v10 + b0); v11 = tanhf(v11 + b1);
            }
            if (MODE == TSC || MODE == TTANH) {
                *(float2*)&Cf[(size_t)r0g * ldc + cc] = make_float2(v00, v01);
                *(float2*)&Cf[(size_t)r1g * ldc + cc] = make_float2(v10, v11);
            } else {
                unsigned short l00, l01, l10, l11;
                unsigned short h00 = sp(v00, &l00), h01 = sp(v01, &l01);
                unsigned short h10 = sp(v10, &l10), h11 = sp(v11, &l11);
                ushort2 H0; H0.x = h00; H0.y = h01;
                ushort2 H1; H1.x = h10; H1.y = h11;
                ushort2 L0; L0.x = l00; L0.y = l01;
                ushort2 L1; L1.x = l10; L1.y = l11;
                *(ushort2*)(Chi + (size_t)r0g * ldc + cc) = H0;
                *(ushort2*)(Chi + (size_t)r1g * ldc + cc) = H1;
                *(ushort2*)(Clo + (size_t)r0g * ldc + cc) = L0;
                *(ushort2*)(Clo + (size_t)r1g * ldc + cc) = L1;
            }
        }
    }
#undef LOADCH
#undef STORECH
}

// ------------------------- launch --------------------------------------------
extern "C" void kernel_launch(void* const* d_in, const int* in_sizes, int n_in,
                              void* d_out, int out_size) {
    const float* query = (const float*)d_in[0];
    const float* value = (const float*)d_in[1];
    const float* pa    = (const float*)d_in[2];
    const float* cw    = (const float*)d_in[3];
    const float* cb    = (const float*)d_in[4];
    const float* Wq    = (const float*)d_in[5];
    const float* bq    = (const float*)d_in[6];
    const float* Wv    = (const float*)d_in[7];
    const float* Wloc  = (const float*)d_in[8];
    const float* bias  = (const float*)d_in[9];
    const float* Wout  = (const float*)d_in[10];
    const float* bout  = (const float*)d_in[11];
    const float* swq   = (const float*)d_in[12];
    const float* sbq   = (const float*)d_in[13];
    const float* swk   = (const float*)d_in[14];
    const float* sbk   = (const float*)d_in[15];
    const float* swv   = (const float*)d_in[16];
    const float* sbv   = (const float*)d_in[17];

    float* out = (float*)d_out;
    const size_t OUT_ELEMS  = (size_t)16 * 512 * 1024;
    const size_t ATTN_ELEMS = (size_t)64 * 512 * 512;

    float *pW2k, *pW2v, *pCk, *pCv, *pBq2, *pATT;
    cudaGetSymbolAddress((void**)&pW2k, dW2k);
    cudaGetSymbolAddress((void**)&pW2v, dW2v);
    cudaGetSymbolAddress((void**)&pCk, dCk);
    cudaGetSymbolAddress((void**)&pCv, dCv);
    cudaGetSymbolAddress((void**)&pBq2, dBq2);
    cudaGetSymbolAddress((void**)&pATT, dATTN);
#define GETBF(p, sym) BF* p; cudaGetSymbolAddress((void**)&p, sym)
    GETBF(qhi, g_qhi);     GETBF(qlo, g_qlo);
    GETBF(vhi, g_vhi);     GETBF(vlo, g_vlo);
    GETBF(Wqhi, g_Wqhi);   GETBF(Wqlo, g_Wqlo);
    GETBF(Wvhi, g_Wvhi);   GETBF(Wvlo, g_Wvlo);
    GETBF(sqThi, g_sqThi); GETBF(sqTlo, g_sqTlo);
    GETBF(skThi, g_skThi); GETBF(skTlo, g_skTlo);
    GETBF(svThi, g_svThi); GETBF(svTlo, g_svTlo);
    GETBF(WoThi, g_WoThi); GETBF(WoTlo, g_WoTlo);
    GETBF(Wq2Thi, g_Wq2Thi); GETBF(Wq2Tlo, g_Wq2Tlo);
    GETBF(WvkThi, g_WvkThi); GETBF(WvkTlo, g_WvkTlo);
    GETBF(WvvThi, g_WvvThi); GETBF(WvvTlo, g_WvvTlo);
    GETBF(qqhi, g_qqhi);   GETBF(qqlo, g_qqlo);
    GETBF(kkhi, g_kkhi);   GETBF(kklo, g_kklo);
    GETBF(vvhi, g_vvhi);   GETBF(vvlo, g_vvlo);
    GETBF(vvThi, g_vvThi); GETBF(vvTlo, g_vvTlo);
    GETBF(athi, g_athi);   GETBF(atlo, g_atlo);
    GETBF(cxhi, g_cxhi);   GETBF(cxlo, g_cxlo);
#undef GETBF

    float* attn = ((size_t)out_size >= OUT_ELEMS + ATTN_ELEMS) ? (out + OUT_ELEMS) : pATT;

    dim3 T(256);
    // precompute + splits
    prep1<<<1, 256>>>(cw, cb, Wloc);
    prep2<<<18, 256>>>(swq, sbq, swk, sbk, swv, sbv, bias, bq);
    splitKn<<<8192, 256>>>((const float4*)query, (ushort4*)qhi, (ushort4*)qlo, 2097152);
    splitKn<<<8192, 256>>>((const float4*)value, (ushort4*)vhi, (ushort4*)vlo, 2097152);
    splitKn<<<1024, 256>>>((const float4*)Wq, (ushort4*)Wqhi, (ushort4*)Wqlo, 262144);
    splitKn<<<1024, 256>>>((const float4*)Wv, (ushort4*)Wvhi, (ushort4*)Wvlo, 262144);
    splitT<<<dim3(8, 8), 256>>>(swq, (unsigned short*)sqThi, (unsigned short*)sqTlo, 256, 256);
    splitT<<<dim3(8, 8), 256>>>(swk, (unsigned short*)skThi, (unsigned short*)skTlo, 256, 256);
    splitT<<<dim3(8, 8), 256>>>(swv, (unsigned short*)svThi, (unsigned short*)svTlo, 256, 256);
    splitT<<<dim3(32, 64), 256>>>(Wout, (unsigned short*)WoThi, (unsigned short*)WoTlo, 2048, 1024);

    // weight folds (per head z): Wx2T[d'][e]
    gemmTC<TFOLD><<<dim3(8, 2, 4), T>>>(sqThi, sqTlo, 0, 0, Wqhi, Wqlo,
        Wq2Thi, Wq2Tlo, 0, 256, 256, 1024, 1024, 0, 0, 0, 0);
    gemmTC<TFOLD><<<dim3(8, 2, 4), T>>>(skThi, skTlo, 0, 0, Wvhi, Wvlo,
        WvkThi, WvkTlo, 0, 256, 256, 1024, 1024, 0, 0, 0, 0);
    gemmTC<TFOLD><<<dim3(8, 2, 4), T>>>(svThi, svTlo, 0, 0, Wvhi, Wvlo,
        WvvThi, WvvTlo, 0, 256, 256, 1024, 1024, 0, 0, 0, 0);

    // qq / kk / vv: 8192 x 1024, K=1024, fused epilogues emit bf16 splits
    gemmTC<TQQ><<<dim3(8, 64, 1), T>>>(qhi, qlo, 0, 0, Wq2Thi, Wq2Tlo,
        qqhi, qqlo, 0, 1024, 1024, 1024, 1024, pBq2, 0, 0, 0);
    gemmTC<TKK><<<dim3(8, 64, 1), T>>>(vhi, vlo, 0, 0, WvkThi, WvkTlo,
        kkhi, kklo, 0, 1024, 1024, 1024, 1024, 0, pa, pW2k, pCk);
    gemmTC<TVV><<<dim3(8, 64, 1), T>>>(vhi, vlo, 0, 0, WvvThi, WvvTlo,
        vvhi, vvlo, 0, 1024, 1024, 1024, 1024, 0, pa, pW2v, pCv);
    transVV<<<dim3(16, 8, 64), 256>>>((unsigned short*)vvhi, (unsigned short*)vvlo,
                                      (unsigned short*)vvThi, (unsigned short*)vvTlo);

    // attention
    gemmTC<TSC><<<dim3(4, 4, 64), T>>>(qqhi, qqlo, 0, 0, kkhi, kklo,
        0, 0, attn, 256, 1024, 1024, 512, 0, 0, 0, 0);
    softmax512<<<64 * 512, 128>>>(attn, (ushort4*)athi, (ushort4*)atlo);
    gemmTC<TCTX><<<dim3(2, 4, 64), T>>>(athi, atlo, 0, 0, vvThi, vvTlo,
        cxhi, cxlo, 0, 512, 512, 512, 1024, 0, 0, 0, 0);

    // out = tanh([ctx, query] @ Wout + bout)
    gemmTC<TTANH><<<dim3(8, 64, 1), T>>>(cxhi, cxlo, qhi, qlo, WoThi, WoTlo,
        0, 0, out, 2048, 1024, 2048, 1024, bout, 0, 0, 0);
}

// round 9
// speedup vs baseline: 2.2572x; 1.2464x over previous
#include <cuda_runtime.h>
#include <cuda_bf16.h>
#include <math.h>
#include <stdint.h>

typedef __nv_bfloat16 BF;

// Problem constants: B=16, QL=VL=512, HID=1024, NH=4, DIM=256, CH=10
#define SZ_ACT (8192 * 1024)
#define SZ_ATT (64 * 512 * 512)

// GEMM modes
#define TFOLD 0
#define TQQ   1
#define TKK   2
#define TVV   3
#define TSC   4
#define TCTX  5
#define TTANH 6

// Dynamic SMEM: 2 stages x (Ahi,Alo,Bhi,Blo) x 128 rows x 40 halves
#define STGB   40960
#define SMEMDYN (2 * STGB)

// ------------------------- device scratch ------------------------------------
__device__ float dW2[768], dB2[256], dW2k[768], dW2v[768], dCk[1024], dCv[1024], dBq2[1024];
__device__ float dATTN[SZ_ATT];

__device__ __align__(256) BF g_qhi[SZ_ACT],   g_qlo[SZ_ACT];
__device__ __align__(256) BF g_vhi[SZ_ACT],   g_vlo[SZ_ACT];
__device__ __align__(256) BF g_Wqhi[1048576], g_Wqlo[1048576];
__device__ __align__(256) BF g_Wvhi[1048576], g_Wvlo[1048576];
__device__ __align__(256) BF g_sqThi[65536],  g_sqTlo[65536];
__device__ __align__(256) BF g_skThi[65536],  g_skTlo[65536];
__device__ __align__(256) BF g_svThi[65536],  g_svTlo[65536];
__device__ __align__(256) BF g_WoThi[2097152], g_WoTlo[2097152];
__device__ __align__(256) BF g_Wq2Thi[1048576], g_Wq2Tlo[1048576];
__device__ __align__(256) BF g_WvkThi[1048576], g_WvkTlo[1048576];
__device__ __align__(256) BF g_WvvThi[1048576], g_WvvTlo[1048576];
__device__ __align__(256) BF g_qqhi[SZ_ACT],  g_qqlo[SZ_ACT];
__device__ __align__(256) BF g_kkhi[SZ_ACT],  g_kklo[SZ_ACT];
__device__ __align__(256) BF g_vvhi[SZ_ACT],  g_vvlo[SZ_ACT];
__device__ __align__(256) BF g_vvThi[SZ_ACT], g_vvTlo[SZ_ACT];
__device__ __align__(256) BF g_athi[SZ_ATT],  g_atlo[SZ_ATT];
__device__ __align__(256) BF g_cxhi[SZ_ACT],  g_cxlo[SZ_ACT];

// ------------------------- helpers -------------------------------------------
__device__ __forceinline__ uint32_t smem_u32(const void* p) {
    uint32_t a;
    asm("{ .reg .u64 t; cvta.to.shared.u64 t, %1; cvt.u32.u64 %0, t; }" : "=r"(a) : "l"(p));
    return a;
}
__device__ __forceinline__ unsigned short sp(float v, unsigned short* lo) {
    BF h = __float2bfloat16(v);
    BF l = __float2bfloat16(v - __bfloat162float(h));
    *lo = __bfloat16_as_ushort(l);
    return __bfloat16_as_ushort(h);
}

#define LDSM4(r0, r1, r2, r3, a) \
    asm volatile("ldmatrix.sync.aligned.m8n8.x4.shared.b16 {%0,%1,%2,%3}, [%4];" \
        : "=r"(r0), "=r"(r1), "=r"(r2), "=r"(r3) : "r"(a))
#define LDSM2(r0, r1, a) \
    asm volatile("ldmatrix.sync.aligned.m8n8.x2.shared.b16 {%0,%1}, [%2];" \
        : "=r"(r0), "=r"(r1) : "r"(a))
#define MMA16816(c, a, b) \
    asm volatile("mma.sync.aligned.m16n8k16.row.col.f32.bf16.bf16.f32 " \
        "{%0,%1,%2,%3}, {%4,%5,%6,%7}, {%8,%9}, {%0,%1,%2,%3};" \
        : "+f"((c)[0]), "+f"((c)[1]), "+f"((c)[2]), "+f"((c)[3]) \
        : "r"((a)[0]), "r"((a)[1]), "r"((a)[2]), "r"((a)[3]), "r"((b)[0]), "r"((b)[1]))
#define CPA16(sa, ga) \
    asm volatile("cp.async.cg.shared.global [%0], [%1], 16;" :: "r"(sa), "l"(ga))
#define CPCOMMIT() asm volatile("cp.async.commit_group;" ::: "memory")
#define CPWAIT0()  asm volatile("cp.async.wait_group 0;" ::: "memory")

// ------------------------- tiny precompute -----------------------------------
__global__ void prep1(const float* __restrict__ cw, const float* __restrict__ cb,
                      const float* __restrict__ Wloc) {
    int d = threadIdx.x;  // 256
    float w0 = 0.f, w1 = 0.f, w2 = 0.f, b2 = 0.f;
    for (int c = 0; c < 10; c++) {
        float wl = Wloc[c * 256 + d];
        w0 += cw[c * 3 + 0] * wl; w1 += cw[c * 3 + 1] * wl; w2 += cw[c * 3 + 2] * wl;
        b2 += cb[c] * wl;
    }
    dW2[d] = w0; dW2[256 + d] = w1; dW2[512 + d] = w2; dB2[d] = b2;
}

__global__ void prep2(const float* __restrict__ swq, const float* __restrict__ sbq,
                      const float* __restrict__ swk, const float* __restrict__ sbk,
                      const float* __restrict__ swv, const float* __restrict__ sbv,
                      const float* __restrict__ bias, const float* __restrict__ bq) {
    int idx = blockIdx.x * 256 + threadIdx.x;
    if (idx < 768) {
        int k = idx >> 8, d = idx & 255; float s = 0.f;
        for (int e = 0; e < 256; e++) s += dW2[k * 256 + e] * swk[e * 256 + d];
        dW2k[idx] = s;
    } else if (idx < 1536) {
        int t = idx - 768; int k = t >> 8, d = t & 255; float s = 0.f;
        for (int e = 0; e < 256; e++) s += dW2[k * 256 + e] * swv[e * 256 + d];
        dW2v[t] = s;
    } else if (idx < 2560) {
        int t = idx - 1536; int h = t >> 8, d = t & 255; float s = sbk[d];
        for (int e = 0; e < 256; e++) s += (bias[h * 256 + e] + dB2[e]) * swk[e * 256 + d];
        dCk[t] = s;
    } else if (idx < 3584) {
        int t = idx - 2560; int h = t >> 8, d = t & 255; float s = sbv[d];
        for (int e = 0; e < 256; e++) s += (bias[h * 256 + e] + dB2[e]) * swv[e * 256 + d];
        dCv[t] = s;
    } else if (idx < 4608) {
        int t = idx - 3584; int h = t >> 8, d = t & 255; float s = sbq[d];
        for (int e = 0; e < 256; e++) s += bq[h * 256 + e] * swq[e * 256 + d];
        dBq2[t] = s;
    }
}

// ------------------------- split / transpose ---------------------------------
__global__ void splitKn(const float4* __restrict__ s, ushort4* __restrict__ hi,
                        ushort4* __restrict__ lo, int n4) {
    int i = blockIdx.x * 256 + threadIdx.x;
    if (i >= n4) return;
    float4 v = s[i]; ushort4 h, l;
    h.x = sp(v.x, &l.x); h.y = sp(v.y, &l.y); h.z = sp(v.z, &l.z); h.w = sp(v.w, &l.w);
    hi[i] = h; lo[i] = l;
}

// out[c][r] = src[r][c]; src R x C row-major, out C x R
__global__ void splitT(const float* __restrict__ s, unsigned short* __restrict__ hi,
                       unsigned short* __restrict__ lo, int R, int C) {
    __shared__ float t[32][33];
    int r0 = blockIdx.y * 32, c0 = blockIdx.x * 32;
    int tx = threadIdx.x & 31, ty = threadIdx.x >> 5;
    for (int y = ty; y < 32; y += 8) t[y][tx] = s[(size_t)(r0 + y) * C + c0 + tx];
    __syncthreads();
    for (int y = ty; y < 32; y += 8) {
        unsigned short l_;
        unsigned short h_ = sp(t[tx][y], &l_);
        size_t o = (size_t)(c0 + y) * R + r0 + tx;
        hi[o] = h_; lo[o] = l_;
    }
}

// vv [(b*512+l)*1024 + h*256+d] -> vvT [((h*16+b)*256+d)*512 + l]
__global__ void transVV(const unsigned short* __restrict__ shi, const unsigned short* __restrict__ slo,
                        unsigned short* __restrict__ thi, unsigned short* __restrict__ tlo) {
    __shared__ unsigned short t0[32][33], t1[32][33];
    int l0 = blockIdx.x * 32, d0 = blockIdx.y * 32;
    int z = blockIdx.z, h = z >> 4, b = z & 15;
    int tx = threadIdx.x & 31, ty = threadIdx.x >> 5;
    for (int y = ty; y < 32; y += 8) {
        size_t s = (size_t)(b * 512 + l0 + y) * 1024 + h * 256 + d0 + tx;
        t0[y][tx] = shi[s]; t1[y][tx] = slo[s];
    }
    __syncthreads();
    for (int y = ty; y < 32; y += 8) {
        size_t o = (size_t)(z * 256 + d0 + y) * 512 + l0 + tx;
        thi[o] = t0[tx][y]; tlo[o] = t1[tx][y];
    }
}

// ------------------------- softmax row-512 + split emit ----------------------
__global__ void softmax512(float* __restrict__ a, ushort4* __restrict__ hi, ushort4* __restrict__ lo) {
    float* p = a + (size_t)blockIdx.x * 512;
    int t = threadIdx.x;  // 128
    float4 v = *(float4*)&p[t * 4];
    float m = fmaxf(fmaxf(v.x, v.y), fmaxf(v.z, v.w));
#pragma unroll
    for (int o = 16; o > 0; o >>= 1) m = fmaxf(m, __shfl_xor_sync(0xffffffffu, m, o));
    __shared__ float sh[4], sh2[4];
    int w = t >> 5, lane = t & 31;
    if (lane == 0) sh[w] = m;
    __syncthreads();
    m = fmaxf(fmaxf(sh[0], sh[1]), fmaxf(sh[2], sh[3]));
    v.x = __expf(v.x - m); v.y = __expf(v.y - m); v.z = __expf(v.z - m); v.w = __expf(v.w - m);
    float s = v.x + v.y + v.z + v.w;
#pragma unroll
    for (int o = 16; o > 0; o >>= 1) s += __shfl_xor_sync(0xffffffffu, s, o);
    if (lane == 0) sh2[w] = s;
    __syncthreads();
    s = sh2[0] + sh2[1] + sh2[2] + sh2[3];
    float inv = 1.f / s;
    v.x *= inv; v.y *= inv; v.z *= inv; v.w *= inv;
    *(float4*)&p[t * 4] = v;
    ushort4 h4, l4;
    h4.x = sp(v.x, &l4.x); h4.y = sp(v.y, &l4.y); h4.z = sp(v.z, &l4.z); h4.w = sp(v.w, &l4.w);
    hi[(size_t)blockIdx.x * 128 + t] = h4;
    lo[(size_t)blockIdx.x * 128 + t] = l4;
}

// ------------------------- mma.sync split-precision GEMM ---------------------
// D[m,n] = sum_k A[m,k]*B[n,k]; per 32-wide K-chunk all 3 bf16 passes:
// AhiBhi + AloBhi + AhiBlo, cp.async double-buffered, 1 sync pair/chunk.
template <int MODE>
__global__ __launch_bounds__(256, 2)
void gemmTC(const BF* __restrict__ Ahi, const BF* __restrict__ Alo,
            const BF* __restrict__ A2hi, const BF* __restrict__ A2lo,
            const BF* __restrict__ Bhi, const BF* __restrict__ Blo,
            BF* __restrict__ Chi, BF* __restrict__ Clo, float* __restrict__ Cf,
            int K, int lda, int ldb, int ldc,
            const float* __restrict__ bias, const float* __restrict__ pa,
            const float* __restrict__ W2x, const float* __restrict__ cx) {
    extern __shared__ BF smem[];
    const int tid = threadIdx.x;
    const int lane = tid & 31, wid = tid >> 5;
    const int wm = (wid >> 2) * 64, wn = (wid & 3) * 32;
    const int bm = blockIdx.y * 128, bn = blockIdx.x * 128;
    const int z = blockIdx.z;

    if (MODE == TFOLD) {
        Bhi += z * 256; Blo += z * 256;
        Chi += (size_t)z * 256 * ldc; Clo += (size_t)z * 256 * ldc;
    }
    if (MODE == TSC) {
        int h = z >> 4, b = z & 15;
        size_t o = (size_t)b * 512 * 1024 + h * 256;
        Ahi += o; Alo += o; Bhi += o; Blo += o;
        Cf += (size_t)z * 262144;
    }
    if (MODE == TCTX) {
        int h = z >> 4, b = z & 15;
        size_t oa = (size_t)z * 262144; Ahi += oa; Alo += oa;
        size_t ob = (size_t)z * 131072; Bhi += ob; Blo += ob;
        size_t oc = (size_t)b * 512 * 1024 + h * 256; Chi += oc; Clo += oc;
    }

    float acc[4][4][4];
#pragma unroll
    for (int a = 0; a < 4; a++)
#pragma unroll
        for (int b = 0; b < 4; b++)
#pragma unroll
            for (int c = 0; c < 4; c++) acc[a][b][c] = 0.f;

    const int NC = K >> 5;  // 32-wide K-chunks
    uint32_t sbase = smem_u32(smem);

    const int rowL = tid >> 2;          // 0..63 (two row groups per matrix)
    const int segL = (tid & 3) * 8;     // half offset within 32-half row

    // issue chunk c's 4 sub-tiles via cp.async (payload 32KB, 8x16B per thread)
#define ISSUE(c_) do {                                                             \
    int k0 = (c_) << 5;                                                            \
    const BF* ah = Ahi; const BF* al_ = Alo; int ka = k0;                          \
    if (MODE == TTANH && k0 >= 1024) { ah = A2hi; al_ = A2lo; ka = k0 - 1024; }    \
    uint32_t st = sbase + ((c_) & 1) * STGB;                                       \
    _Pragma("unroll")                                                              \
    for (int i = 0; i < 2; i++) {                                                  \
        int row = rowL + i * 64;                                                   \
        uint32_t so = st + (row * 40 + segL) * 2;                                  \
        const BF* ga  = ah  + (size_t)(bm + row) * lda + ka + segL;                \
        const BF* gl  = al_ + (size_t)(bm + row) * lda + ka + segL;                \
        const BF* gbh = Bhi + (size_t)(bn + row) * ldb + k0 + segL;                \
        const BF* gbl = Blo + (size_t)(bn + row) * ldb + k0 + segL;                \
        CPA16(so,          ga);                                                    \
        CPA16(so + 10240,  gl);                                                    \
        CPA16(so + 20480,  gbh);                                                   \
        CPA16(so + 30720,  gbl);                                                   \
    }                                                                              \
    CPCOMMIT();                                                                    \
} while (0)

    const int la15 = lane & 15;
    const int laHi = (lane >> 4) << 3;
    const int ttr = lane & 7, ttk = ((lane >> 3) & 1) << 3;

    ISSUE(0);
    for (int c = 0; c < NC; c++) {
        CPWAIT0();
        __syncthreads();
        if (c + 1 < NC) ISSUE(c + 1);
        uint32_t st = sbase + (c & 1) * STGB;
#pragma unroll
        for (int kk = 0; kk < 2; kk++) {
            uint32_t af[4][4], al4[4][4], bh[4][2], bl[4][2];
#pragma unroll
            for (int mt = 0; mt < 4; mt++) {
                uint32_t addr = st + ((wm + mt * 16 + la15) * 40 + kk * 16 + laHi) * 2;
                LDSM4(af[mt][0], af[mt][1], af[mt][2], af[mt][3], addr);
            }
#pragma unroll
            for (int nt = 0; nt < 4; nt++) {
                uint32_t addr = st + 20480 + ((wn + nt * 8 + ttr) * 40 + kk * 16 + ttk) * 2;
                LDSM2(bh[nt][0], bh[nt][1], addr);
            }
#pragma unroll
            for (int mt = 0; mt < 4; mt++)
#pragma unroll
                for (int nt = 0; nt < 4; nt++)
                    MMA16816(acc[mt][nt], af[mt], bh[nt]);
#pragma unroll
            for (int mt = 0; mt < 4; mt++) {
                uint32_t addr = st + 10240 + ((wm + mt * 16 + la15) * 40 + kk * 16 + laHi) * 2;
                LDSM4(al4[mt][0], al4[mt][1], al4[mt][2], al4[mt][3], addr);
            }
#pragma unroll
            for (int mt = 0; mt < 4; mt++)
#pragma unroll
                for (int nt = 0; nt < 4; nt++)
                    MMA16816(acc[mt][nt], al4[mt], bh[nt]);
#pragma unroll
            for (int nt = 0; nt < 4; nt++) {
                uint32_t addr = st + 30720 + ((wn + nt * 8 + ttr) * 40 + kk * 16 + ttk) * 2;
                LDSM2(bl[nt][0], bl[nt][1], addr);
            }
#pragma unroll
            for (int mt = 0; mt < 4; mt++)
#pragma unroll
                for (int nt = 0; nt < 4; nt++)
                    MMA16816(acc[mt][nt], af[mt], bl[nt]);
        }
        __syncthreads();
    }
#undef ISSUE

    // ------------- epilogue: fused math + hi/lo emit, straight from regs -----
#pragma unroll
    for (int mt = 0; mt < 4; mt++) {
        int r0g = bm + wm + mt * 16 + (lane >> 2);
        int r1g = r0g + 8;
        float p0a = 0.f, p1a = 0.f, p2a = 0.f, p0b = 0.f, p1b = 0.f, p2b = 0.f;
        if (MODE == TKK || MODE == TVV) {
            int hh = (bn + wn) >> 8;
            {
                int b = r0g >> 9, l = r0g & 511;
                size_t pb = (size_t)(b * 4 + hh) * 512;
                p0a = (l >= 1)   ? pa[pb + l - 1] : 0.f;
                p1a =              pa[pb + l];
                p2a = (l <= 510) ? pa[pb + l + 1] : 0.f;
            }
            {
                int b = r1g >> 9, l = r1g & 511;
                size_t pb = (size_t)(b * 4 + hh) * 512;
                p0b = (l >= 1)   ? pa[pb + l - 1] : 0.f;
                p1b =              pa[pb + l];
                p2b = (l <= 510) ? pa[pb + l + 1] : 0.f;
            }
        }
#pragma unroll
        for (int nt = 0; nt < 4; nt++) {
            int cc = bn + wn + nt * 8 + (lane & 3) * 2;
            float v00 = acc[mt][nt][0], v01 = acc[mt][nt][1];
            float v10 = acc[mt][nt][2], v11 = acc[mt][nt][3];
            if (MODE == TQQ) {
                float b0 = bias[cc], b1 = bias[cc + 1];
                v00 += b0; v01 += b1; v10 += b0; v11 += b1;
            }
            if (MODE == TKK || MODE == TVV) {
                int d0 = cc & 255, d1 = d0 + 1;
                float c0 = cx[cc], c1 = cx[cc + 1];
                float w00 = W2x[d0], w10 = W2x[256 + d0], w20 = W2x[512 + d0];
                float w01 = W2x[d1], w11 = W2x[256 + d1], w21 = W2x[512 + d1];
                v00 += c0 + p0a * w00 + p1a * w10 + p2a * w20;
                v01 += c1 + p0a * w01 + p1a * w11 + p2a * w21;
                v10 += c0 + p0b * w00 + p1b * w10 + p2b * w20;
                v11 += c1 + p0b * w01 + p1b * w11 + p2b * w21;
            }
            if (MODE == TSC) { v00 *= 0.0625f; v01 *= 0.0625f; v10 *= 0.0625f; v11 *= 0.0625f; }
            if (MODE == TTANH) {
                float b0 = bias[cc], b1 = bias[cc + 1];
                v00 = tanhf(v00 + b0); v01 = tanhf(v01 + b1);
                v10 = tanhf(v10 + b0); v11 = tanhf(v11 + b1);
            }
            if (MODE == TSC || MODE == TTANH) {
                *(float2*)&Cf[(size_t)r0g * ldc + cc] = make_float2(v00, v01);
                *(float2*)&Cf[(size_t)r1g * ldc + cc] = make_float2(v10, v11);
            } else {
                unsigned short l00, l01, l10, l11;
                unsigned short h00 = sp(v00, &l00), h01 = sp(v01, &l01);
                unsigned short h10 = sp(v10, &l10), h11 = sp(v11, &l11);
                ushort2 H0; H0.x = h00; H0.y = h01;
                ushort2 H1; H1.x = h10; H1.y = h11;
                ushort2 L0; L0.x = l00; L0.y = l01;
                ushort2 L1; L1.x = l10; L1.y = l11;
                *(ushort2*)(Chi + (size_t)r0g * ldc + cc) = H0;
                *(ushort2*)(Chi + (size_t)r1g * ldc + cc) = H1;
                *(ushort2*)(Clo + (size_t)r0g * ldc + cc) = L0;
                *(ushort2*)(Clo + (size_t)r1g * ldc + cc) = L1;
            }
        }
    }
}

// ------------------------- launch --------------------------------------------
extern "C" void kernel_launch(void* const* d_in, const int* in_sizes, int n_in,
                              void* d_out, int out_size) {
    const float* query = (const float*)d_in[0];
    const float* value = (const float*)d_in[1];
    const float* pa    = (const float*)d_in[2];
    const float* cw    = (const float*)d_in[3];
    const float* cb    = (const float*)d_in[4];
    const float* Wq    = (const float*)d_in[5];
    const float* bq    = (const float*)d_in[6];
    const float* Wv    = (const float*)d_in[7];
    const float* Wloc  = (const float*)d_in[8];
    const float* bias  = (const float*)d_in[9];
    const float* Wout  = (const float*)d_in[10];
    const float* bout  = (const float*)d_in[11];
    const float* swq   = (const float*)d_in[12];
    const float* sbq   = (const float*)d_in[13];
    const float* swk   = (const float*)d_in[14];
    const float* sbk   = (const float*)d_in[15];
    const float* swv   = (const float*)d_in[16];
    const float* sbv   = (const float*)d_in[17];

    float* out = (float*)d_out;
    const size_t OUT_ELEMS  = (size_t)16 * 512 * 1024;
    const size_t ATTN_ELEMS = (size_t)64 * 512 * 512;

    float *pW2k, *pW2v, *pCk, *pCv, *pBq2, *pATT;
    cudaGetSymbolAddress((void**)&pW2k, dW2k);
    cudaGetSymbolAddress((void**)&pW2v, dW2v);
    cudaGetSymbolAddress((void**)&pCk, dCk);
    cudaGetSymbolAddress((void**)&pCv, dCv);
    cudaGetSymbolAddress((void**)&pBq2, dBq2);
    cudaGetSymbolAddress((void**)&pATT, dATTN);
#define GETBF(p, sym) BF* p; cudaGetSymbolAddress((void**)&p, sym)
    GETBF(qhi, g_qhi);     GETBF(qlo, g_qlo);
    GETBF(vhi, g_vhi);     GETBF(vlo, g_vlo);
    GETBF(Wqhi, g_Wqhi);   GETBF(Wqlo, g_Wqlo);
    GETBF(Wvhi, g_Wvhi);   GETBF(Wvlo, g_Wvlo);
    GETBF(sqThi, g_sqThi); GETBF(sqTlo, g_sqTlo);
    GETBF(skThi, g_skThi); GETBF(skTlo, g_skTlo);
    GETBF(svThi, g_svThi); GETBF(svTlo, g_svTlo);
    GETBF(WoThi, g_WoThi); GETBF(WoTlo, g_WoTlo);
    GETBF(Wq2Thi, g_Wq2Thi); GETBF(Wq2Tlo, g_Wq2Tlo);
    GETBF(WvkThi, g_WvkThi); GETBF(WvkTlo, g_WvkTlo);
    GETBF(WvvThi, g_WvvThi); GETBF(WvvTlo, g_WvvTlo);
    GETBF(qqhi, g_qqhi);   GETBF(qqlo, g_qqlo);
    GETBF(kkhi, g_kkhi);   GETBF(kklo, g_kklo);
    GETBF(vvhi, g_vvhi);   GETBF(vvlo, g_vvlo);
    GETBF(vvThi, g_vvThi); GETBF(vvTlo, g_vvTlo);
    GETBF(athi, g_athi);   GETBF(atlo, g_atlo);
    GETBF(cxhi, g_cxhi);   GETBF(cxlo, g_cxlo);
#undef GETBF

    float* attn = ((size_t)out_size >= OUT_ELEMS + ATTN_ELEMS) ? (out + OUT_ELEMS) : pATT;

    // Not stream ops; deterministic on every call (no static guards allowed).
    cudaFuncSetAttribute(gemmTC<TFOLD>, cudaFuncAttributeMaxDynamicSharedMemorySize, SMEMDYN);
    cudaFuncSetAttribute(gemmTC<TQQ>,   cudaFuncAttributeMaxDynamicSharedMemorySize, SMEMDYN);
    cudaFuncSetAttribute(gemmTC<TKK>,   cudaFuncAttributeMaxDynamicSharedMemorySize, SMEMDYN);
    cudaFuncSetAttribute(gemmTC<TVV>,   cudaFuncAttributeMaxDynamicSharedMemorySize, SMEMDYN);
    cudaFuncSetAttribute(gemmTC<TSC>,   cudaFuncAttributeMaxDynamicSharedMemorySize, SMEMDYN);
    cudaFuncSetAttribute(gemmTC<TCTX>,  cudaFuncAttributeMaxDynamicSharedMemorySize, SMEMDYN);
    cudaFuncSetAttribute(gemmTC<TTANH>, cudaFuncAttributeMaxDynamicSharedMemorySize, SMEMDYN);

    dim3 T(256);
    // precompute + splits
    prep1<<<1, 256>>>(cw, cb, Wloc);
    prep2<<<18, 256>>>(swq, sbq, swk, sbk, swv, sbv, bias, bq);
    splitKn<<<8192, 256>>>((const float4*)query, (ushort4*)qhi, (ushort4*)qlo, 2097152);
    splitKn<<<8192, 256>>>((const float4*)value, (ushort4*)vhi, (ushort4*)vlo, 2097152);
    splitKn<<<1024, 256>>>((const float4*)Wq, (ushort4*)Wqhi, (ushort4*)Wqlo, 262144);
    splitKn<<<1024, 256>>>((const float4*)Wv, (ushort4*)Wvhi, (ushort4*)Wvlo, 262144);
    splitT<<<dim3(8, 8), 256>>>(swq, (unsigned short*)sqThi, (unsigned short*)sqTlo, 256, 256);
    splitT<<<dim3(8, 8), 256>>>(swk, (unsigned short*)skThi, (unsigned short*)skTlo, 256, 256);
    splitT<<<dim3(8, 8), 256>>>(swv, (unsigned short*)svThi, (unsigned short*)svTlo, 256, 256);
    splitT<<<dim3(32, 64), 256>>>(Wout, (unsigned short*)WoThi, (unsigned short*)WoTlo, 2048, 1024);

    // weight folds (per head z): Wx2T[d'][e]
    gemmTC<TFOLD><<<dim3(8, 2, 4), T, SMEMDYN>>>(sqThi, sqTlo, 0, 0, Wqhi, Wqlo,
        Wq2Thi, Wq2Tlo, 0, 256, 256, 1024, 1024, 0, 0, 0, 0);
    gemmTC<TFOLD><<<dim3(8, 2, 4), T, SMEMDYN>>>(skThi, skTlo, 0, 0, Wvhi, Wvlo,
        WvkThi, WvkTlo, 0, 256, 256, 1024, 1024, 0, 0, 0, 0);
    gemmTC<TFOLD><<<dim3(8, 2, 4), T, SMEMDYN>>>(svThi, svTlo, 0, 0, Wvhi, Wvlo,
        WvvThi, WvvTlo, 0, 256, 256, 1024, 1024, 0, 0, 0, 0);

    // qq / kk / vv: 8192 x 1024, K=1024, fused epilogues emit bf16 splits
    gemmTC<TQQ><<<dim3(8, 64, 1), T, SMEMDYN>>>(qhi, qlo, 0, 0, Wq2Thi, Wq2Tlo,
        qqhi, qqlo, 0, 1024, 1024, 1024, 1024, pBq2, 0, 0, 0);
    gemmTC<TKK><<<dim3(8, 64, 1), T, SMEMDYN>>>(vhi, vlo, 0, 0, WvkThi, WvkTlo,
        kkhi, kklo, 0, 1024, 1024, 1024, 1024, 0, pa, pW2k, pCk);
    gemmTC<TVV><<<dim3(8, 64, 1), T, SMEMDYN>>>(vhi, vlo, 0, 0, WvvThi, WvvTlo,
        vvhi, vvlo, 0, 1024, 1024, 1024, 1024, 0, pa, pW2v, pCv);
    transVV<<<dim3(16, 8, 64), 256>>>((unsigned short*)vvhi, (unsigned short*)vvlo,
                                      (unsigned short*)vvThi, (unsigned short*)vvTlo);

    // attention
    gemmTC<TSC><<<dim3(4, 4, 64), T, SMEMDYN>>>(qqhi, qqlo, 0, 0, kkhi, kklo,
        0, 0, attn, 256, 1024, 1024, 512, 0, 0, 0, 0);
    softmax512<<<64 * 512, 128>>>(attn, (ushort4*)athi, (ushort4*)atlo);
    gemmTC<TCTX><<<dim3(2, 4, 64), T, SMEMDYN>>>(athi, atlo, 0, 0, vvThi, vvTlo,
        cxhi, cxlo, 0, 512, 512, 512, 1024, 0, 0, 0, 0);

    // out = tanh([ctx, query] @ Wout + bout)
    gemmTC<TTANH><<<dim3(8, 64, 1), T, SMEMDYN>>>(cxhi, cxlo, qhi, qlo, WoThi, WoTlo,
        0, 0, out, 2048, 1024, 2048, 1024, bout, 0, 0, 0);
}

// round 10
// speedup vs baseline: 4.5954x; 2.0359x over previous
#include <cuda_runtime.h>
#include <cuda_fp16.h>
#include <math.h>
#include <stdint.h>

typedef __half H;

// Problem constants: B=16, QL=VL=512, HID=1024, NH=4, DIM=256, CH=10
#define SZ_ACT (8192 * 1024)
#define SZ_ATT (64 * 512 * 512)

// GEMM modes
#define TFOLD 0
#define TQQ   1
#define TKK   2
#define TVV   3
#define TSC   4
#define TCTX  5
#define TTANH 6

// Dynamic SMEM: 3 stages x (A,B) x 128 rows x 40 halves
#define STGB    20480
#define SMEMDYN (3 * STGB)

// ------------------------- device scratch ------------------------------------
__device__ float dW2[768], dB2[256], dW2k[768], dW2v[768], dCk[1024], dCv[1024], dBq2[1024];
__device__ float dATTN[SZ_ATT];

__device__ __align__(256) H g_q[SZ_ACT];
__device__ __align__(256) H g_v[SZ_ACT];
__device__ __align__(256) H g_Wq[1048576];
__device__ __align__(256) H g_Wv[1048576];
__device__ __align__(256) H g_sqT[65536];
__device__ __align__(256) H g_skT[65536];
__device__ __align__(256) H g_svT[65536];
__device__ __align__(256) H g_WoT[2097152];
__device__ __align__(256) H g_Wq2T[1048576];
__device__ __align__(256) H g_WvkT[1048576];
__device__ __align__(256) H g_WvvT[1048576];
__device__ __align__(256) H g_qq[SZ_ACT];
__device__ __align__(256) H g_kk[SZ_ACT];
__device__ __align__(256) H g_vv[SZ_ACT];
__device__ __align__(256) H g_vvT[SZ_ACT];
__device__ __align__(256) H g_at[SZ_ATT];
__device__ __align__(256) H g_cx[SZ_ACT];

// ------------------------- helpers -------------------------------------------
__device__ __forceinline__ uint32_t smem_u32(const void* p) {
    uint32_t a;
    asm("{ .reg .u64 t; cvta.to.shared.u64 t, %1; cvt.u32.u64 %0, t; }" : "=r"(a) : "l"(p));
    return a;
}

#define LDSM4(r0, r1, r2, r3, a) \
    asm volatile("ldmatrix.sync.aligned.m8n8.x4.shared.b16 {%0,%1,%2,%3}, [%4];" \
        : "=r"(r0), "=r"(r1), "=r"(r2), "=r"(r3) : "r"(a))
#define LDSM2(r0, r1, a) \
    asm volatile("ldmatrix.sync.aligned.m8n8.x2.shared.b16 {%0,%1}, [%2];" \
        : "=r"(r0), "=r"(r1) : "r"(a))
#define MMA16816(c, a, b) \
    asm volatile("mma.sync.aligned.m16n8k16.row.col.f32.f16.f16.f32 " \
        "{%0,%1,%2,%3}, {%4,%5,%6,%7}, {%8,%9}, {%0,%1,%2,%3};" \
        : "+f"((c)[0]), "+f"((c)[1]), "+f"((c)[2]), "+f"((c)[3]) \
        : "r"((a)[0]), "r"((a)[1]), "r"((a)[2]), "r"((a)[3]), "r"((b)[0]), "r"((b)[1]))
#define CPA16(sa, ga) \
    asm volatile("cp.async.cg.shared.global [%0], [%1], 16;" :: "r"(sa), "l"(ga))
#define CPCOMMIT() asm volatile("cp.async.commit_group;" ::: "memory")
#define CPWAIT0()  asm volatile("cp.async.wait_group 0;" ::: "memory")
#define CPWAIT1()  asm volatile("cp.async.wait_group 1;" ::: "memory")

// ------------------------- tiny precompute -----------------------------------
__global__ void prep1(const float* __restrict__ cw, const float* __restrict__ cb,
                      const float* __restrict__ Wloc) {
    int d = threadIdx.x;  // 256
    float w0 = 0.f, w1 = 0.f, w2 = 0.f, b2 = 0.f;
    for (int c = 0; c < 10; c++) {
        float wl = Wloc[c * 256 + d];
        w0 += cw[c * 3 + 0] * wl; w1 += cw[c * 3 + 1] * wl; w2 += cw[c * 3 + 2] * wl;
        b2 += cb[c] * wl;
    }
    dW2[d] = w0; dW2[256 + d] = w1; dW2[512 + d] = w2; dB2[d] = b2;
}

__global__ void prep2(const float* __restrict__ swq, const float* __restrict__ sbq,
                      const float* __restrict__ swk, const float* __restrict__ sbk,
                      const float* __restrict__ swv, const float* __restrict__ sbv,
                      const float* __restrict__ bias, const float* __restrict__ bq) {
    int idx = blockIdx.x * 256 + threadIdx.x;
    if (idx < 768) {
        int k = idx >> 8, d = idx & 255; float s = 0.f;
        for (int e = 0; e < 256; e++) s += dW2[k * 256 + e] * swk[e * 256 + d];
        dW2k[idx] = s;
    } else if (idx < 1536) {
        int t = idx - 768; int k = t >> 8, d = t & 255; float s = 0.f;
        for (int e = 0; e < 256; e++) s += dW2[k * 256 + e] * swv[e * 256 + d];
        dW2v[t] = s;
    } else if (idx < 2560) {
        int t = idx - 1536; int h = t >> 8, d = t & 255; float s = sbk[d];
        for (int e = 0; e < 256; e++) s += (bias[h * 256 + e] + dB2[e]) * swk[e * 256 + d];
        dCk[t] = s;
    } else if (idx < 3584) {
        int t = idx - 2560; int h = t >> 8, d = t & 255; float s = sbv[d];
        for (int e = 0; e < 256; e++) s += (bias[h * 256 + e] + dB2[e]) * swv[e * 256 + d];
        dCv[t] = s;
    } else if (idx < 4608) {
        int t = idx - 3584; int h = t >> 8, d = t & 255; float s = sbq[d];
        for (int e = 0; e < 256; e++) s += bq[h * 256 + e] * swq[e * 256 + d];
        dBq2[t] = s;
    }
}

// ------------------------- convert / transpose -------------------------------
__global__ void cvtKn(const float4* __restrict__ s, __half2* __restrict__ o, int n4) {
    int i = blockIdx.x * 256 + threadIdx.x;
    if (i >= n4) return;
    float4 v = s[i];
    o[i * 2 + 0] = __floats2half2_rn(v.x, v.y);
    o[i * 2 + 1] = __floats2half2_rn(v.z, v.w);
}

// out[c][r] = src[r][c]; src R x C row-major, out C x R
__global__ void cvtT(const float* __restrict__ s, H* __restrict__ o, int R, int C) {
    __shared__ float t[32][33];
    int r0 = blockIdx.y * 32, c0 = blockIdx.x * 32;
    int tx = threadIdx.x & 31, ty = threadIdx.x >> 5;
    for (int y = ty; y < 32; y += 8) t[y][tx] = s[(size_t)(r0 + y) * C + c0 + tx];
    __syncthreads();
    for (int y = ty; y < 32; y += 8)
        o[(size_t)(c0 + y) * R + r0 + tx] = __float2half(t[tx][y]);
}

// vv [(b*512+l)*1024 + h*256+d] -> vvT [((h*16+b)*256+d)*512 + l]
__global__ void transVV(const H* __restrict__ s, H* __restrict__ o) {
    __shared__ H t0[32][33];
    int l0 = blockIdx.x * 32, d0 = blockIdx.y * 32;
    int z = blockIdx.z, h = z >> 4, b = z & 15;
    int tx = threadIdx.x & 31, ty = threadIdx.x >> 5;
    for (int y = ty; y < 32; y += 8)
        t0[y][tx] = s[(size_t)(b * 512 + l0 + y) * 1024 + h * 256 + d0 + tx];
    __syncthreads();
    for (int y = ty; y < 32; y += 8)
        o[(size_t)(z * 256 + d0 + y) * 512 + l0 + tx] = t0[tx][y];
}

// ------------------------- softmax row-512 + fp16 emit -----------------------
__global__ void softmax512(float* __restrict__ a, __half2* __restrict__ ho) {
    float* p = a + (size_t)blockIdx.x * 512;
    int t = threadIdx.x;  // 128
    float4 v = *(float4*)&p[t * 4];
    float m = fmaxf(fmaxf(v.x, v.y), fmaxf(v.z, v.w));
#pragma unroll
    for (int o = 16; o > 0; o >>= 1) m = fmaxf(m, __shfl_xor_sync(0xffffffffu, m, o));
    __shared__ float sh[4], sh2[4];
    int w = t >> 5, lane = t & 31;
    if (lane == 0) sh[w] = m;
    __syncthreads();
    m = fmaxf(fmaxf(sh[0], sh[1]), fmaxf(sh[2], sh[3]));
    v.x = __expf(v.x - m); v.y = __expf(v.y - m); v.z = __expf(v.z - m); v.w = __expf(v.w - m);
    float s = v.x + v.y + v.z + v.w;
#pragma unroll
    for (int o = 16; o > 0; o >>= 1) s += __shfl_xor_sync(0xffffffffu, s, o);
    if (lane == 0) sh2[w] = s;
    __syncthreads();
    s = sh2[0] + sh2[1] + sh2[2] + sh2[3];
    float inv = 1.f / s;
    v.x *= inv; v.y *= inv; v.z *= inv; v.w *= inv;
    *(float4*)&p[t * 4] = v;
    size_t base = (size_t)blockIdx.x * 256 + t * 2;
    ho[base + 0] = __floats2half2_rn(v.x, v.y);
    ho[base + 1] = __floats2half2_rn(v.z, v.w);
}

// ------------------------- mma.sync fp16 single-pass GEMM --------------------
// D[m,n] = sum_k A[m,k]*B[n,k]; fp16 operands, fp32 accum.
// Tile 128x128, 8 warps (2x4), warp 64x32; 32-wide K-chunks; 3-stage cp.async.
template <int MODE>
__global__ __launch_bounds__(256, 2)
void gemmTC(const H* __restrict__ Ah, const H* __restrict__ A2h,
            const H* __restrict__ Bh,
            H* __restrict__ Ch, float* __restrict__ Cf,
            int K, int lda, int ldb, int ldc,
            const float* __restrict__ bias, const float* __restrict__ pa,
            const float* __restrict__ W2x, const float* __restrict__ cx) {
    extern __shared__ H smem[];
    const int tid = threadIdx.x;
    const int lane = tid & 31, wid = tid >> 5;
    const int wm = (wid >> 2) * 64, wn = (wid & 3) * 32;
    const int bm = blockIdx.y * 128, bn = blockIdx.x * 128;
    const int z = blockIdx.z;

    if (MODE == TFOLD) {
        Bh += z * 256;
        Ch += (size_t)z * 256 * ldc;
    }
    if (MODE == TSC) {
        int h = z >> 4, b = z & 15;
        size_t o = (size_t)b * 512 * 1024 + h * 256;
        Ah += o; Bh += o;
        Cf += (size_t)z * 262144;
    }
    if (MODE == TCTX) {
        int h = z >> 4, b = z & 15;
        Ah += (size_t)z * 262144;
        Bh += (size_t)z * 131072;
        Ch += (size_t)b * 512 * 1024 + h * 256;
    }

    float acc[4][4][4];
#pragma unroll
    for (int a = 0; a < 4; a++)
#pragma unroll
        for (int b = 0; b < 4; b++)
#pragma unroll
            for (int c = 0; c < 4; c++) acc[a][b][c] = 0.f;

    const int NC = K >> 5;  // 32-wide K-chunks
    uint32_t sbase = smem_u32(smem);

    const int rowA = tid >> 2;          // 0..63
    const int segA = (tid & 3) * 8;     // half offset within 32-half row

    // chunk c: A rows [bm,bm+128), B rows [bn,bn+128), 16KB total (4 x 16B/thread)
#define ISSUE(c_) do {                                                             \
    int k0 = (c_) << 5;                                                            \
    const H* ah = Ah; int ka = k0;                                                 \
    if (MODE == TTANH && k0 >= 1024) { ah = A2h; ka = k0 - 1024; }                 \
    uint32_t st = sbase + ((c_) % 3) * STGB;                                       \
    uint32_t so = st + (rowA * 40 + segA) * 2;                                     \
    CPA16(so,        ah + (size_t)(bm + rowA) * lda + ka + segA);                  \
    CPA16(so + 5120, ah + (size_t)(bm + rowA + 64) * lda + ka + segA);             \
    uint32_t sb = st + 10240 + (rowA * 40 + segA) * 2;                             \
    CPA16(sb,        Bh + (size_t)(bn + rowA) * ldb + k0 + segA);                  \
    CPA16(sb + 5120, Bh + (size_t)(bn + rowA + 64) * ldb + k0 + segA);             \
    CPCOMMIT();                                                                    \
} while (0)

    const int la15 = lane & 15;
    const int laHi = (lane >> 4) << 3;
    const int ttr = lane & 7, ttk = ((lane >> 3) & 1) << 3;

    ISSUE(0);
    ISSUE(1);
    for (int c = 0; c < NC; c++) {
        if (c + 2 < NC) { CPWAIT1(); } else { CPWAIT0(); }
        __syncthreads();
        if (c + 2 < NC) ISSUE(c + 2);
        uint32_t st = sbase + (c % 3) * STGB;
#pragma unroll
        for (int kk = 0; kk < 2; kk++) {
            uint32_t af[4][4], bh[4][2];
#pragma unroll
            for (int mt = 0; mt < 4; mt++) {
                uint32_t addr = st + ((wm + mt * 16 + la15) * 40 + kk * 16 + laHi) * 2;
                LDSM4(af[mt][0], af[mt][1], af[mt][2], af[mt][3], addr);
            }
#pragma unroll
            for (int nt = 0; nt < 4; nt++) {
                uint32_t addr = st + 10240 + ((wn + nt * 8 + ttr) * 40 + kk * 16 + ttk) * 2;
                LDSM2(bh[nt][0], bh[nt][1], addr);
            }
#pragma unroll
            for (int mt = 0; mt < 4; mt++)
#pragma unroll
                for (int nt = 0; nt < 4; nt++)
                    MMA16816(acc[mt][nt], af[mt], bh[nt]);
        }
        __syncthreads();
    }
#undef ISSUE

    // ------------- epilogue: fused math + fp16 emit, straight from regs ------
#pragma unroll
    for (int mt = 0; mt < 4; mt++) {
        int r0g = bm + wm + mt * 16 + (lane >> 2);
        int r1g = r0g + 8;
        float p0a = 0.f, p1a = 0.f, p2a = 0.f, p0b = 0.f, p1b = 0.f, p2b = 0.f;
        if (MODE == TKK || MODE == TVV) {
            int hh = (bn + wn) >> 8;
            {
                int b = r0g >> 9, l = r0g & 511;
                size_t pb = (size_t)(b * 4 + hh) * 512;
                p0a = (l >= 1)   ? pa[pb + l - 1] : 0.f;
                p1a =              pa[pb + l];
                p2a = (l <= 510) ? pa[pb + l + 1] : 0.f;
            }
            {
                int b = r1g >> 9, l = r1g & 511;
                size_t pb = (size_t)(b * 4 + hh) * 512;
                p0b = (l >= 1)   ? pa[pb + l - 1] : 0.f;
                p1b =              pa[pb + l];
                p2b = (l <= 510) ? pa[pb + l + 1] : 0.f;
            }
        }
#pragma unroll
        for (int nt = 0; nt < 4; nt++) {
            int cc = bn + wn + nt * 8 + (lane & 3) * 2;
            float v00 = acc[mt][nt][0], v01 = acc[mt][nt][1];
            float v10 = acc[mt][nt][2], v11 = acc[mt][nt][3];
            if (MODE == TQQ) {
                float b0 = bias[cc], b1 = bias[cc + 1];
                v00 += b0; v01 += b1; v10 += b0; v11 += b1;
            }
            if (MODE == TKK || MODE == TVV) {
                int d0 = cc & 255, d1 = d0 + 1;
                float c0 = cx[cc], c1 = cx[cc + 1];
                float w00 = W2x[d0], w10 = W2x[256 + d0], w20 = W2x[512 + d0];
                float w01 = W2x[d1], w11 = W2x[256 + d1], w21 = W2x[512 + d1];
                v00 += c0 + p0a * w00 + p1a * w10 + p2a * w20;
                v01 += c1 + p0a * w01 + p1a * w11 + p2a * w21;
                v10 += c0 + p0b * w00 + p1b * w10 + p2b * w20;
                v11 += c1 + p0b * w01 + p1b * w11 + p2b * w21;
            }
            if (MODE == TSC) { v00 *= 0.0625f; v01 *= 0.0625f; v10 *= 0.0625f; v11 *= 0.0625f; }
            if (MODE == TTANH) {
                float b0 = bias[cc], b1 = bias[cc + 1];
                v00 = tanhf(v00 + b0); v01 = tanhf(v01 + b1);
                v10 = tanhf(v10 + b0); v11 = tanhf(v11 + b1);
            }
            if (MODE == TSC || MODE == TTANH) {
                *(float2*)&Cf[(size_t)r0g * ldc + cc] = make_float2(v00, v01);
                *(float2*)&Cf[(size_t)r1g * ldc + cc] = make_float2(v10, v11);
            } else {
                *(__half2*)(Ch + (size_t)r0g * ldc + cc) = __floats2half2_rn(v00, v01);
                *(__half2*)(Ch + (size_t)r1g * ldc + cc) = __floats2half2_rn(v10, v11);
            }
        }
    }
}

// ------------------------- launch --------------------------------------------
extern "C" void kernel_launch(void* const* d_in, const int* in_sizes, int n_in,
                              void* d_out, int out_size) {
    const float* query = (const float*)d_in[0];
    const float* value = (const float*)d_in[1];
    const float* pa    = (const float*)d_in[2];
    const float* cw    = (const float*)d_in[3];
    const float* cb    = (const float*)d_in[4];
    const float* Wq    = (const float*)d_in[5];
    const float* bq    = (const float*)d_in[6];
    const float* Wv    = (const float*)d_in[7];
    const float* Wloc  = (const float*)d_in[8];
    const float* bias  = (const float*)d_in[9];
    const float* Wout  = (const float*)d_in[10];
    const float* bout  = (const float*)d_in[11];
    const float* swq   = (const float*)d_in[12];
    const float* sbq   = (const float*)d_in[13];
    const float* swk   = (const float*)d_in[14];
    const float* sbk   = (const float*)d_in[15];
    const float* swv   = (const float*)d_in[16];
    const float* sbv   = (const float*)d_in[17];

    float* out = (float*)d_out;
    const size_t OUT_ELEMS  = (size_t)16 * 512 * 1024;
    const size_t ATTN_ELEMS = (size_t)64 * 512 * 512;

    float *pW2k, *pW2v, *pCk, *pCv, *pBq2, *pATT;
    cudaGetSymbolAddress((void**)&pW2k, dW2k);
    cudaGetSymbolAddress((void**)&pW2v, dW2v);
    cudaGetSymbolAddress((void**)&pCk, dCk);
    cudaGetSymbolAddress((void**)&pCv, dCv);
    cudaGetSymbolAddress((void**)&pBq2, dBq2);
    cudaGetSymbolAddress((void**)&pATT, dATTN);
#define GETH(p, sym) H* p; cudaGetSymbolAddress((void**)&p, sym)
    GETH(qh, g_q);       GETH(vh, g_v);
    GETH(Wqh, g_Wq);     GETH(Wvh, g_Wv);
    GETH(sqT, g_sqT);    GETH(skT, g_skT);    GETH(svT, g_svT);
    GETH(WoT, g_WoT);
    GETH(Wq2T, g_Wq2T);  GETH(WvkT, g_WvkT);  GETH(WvvT, g_WvvT);
    GETH(qq, g_qq);      GETH(kk, g_kk);      GETH(vv, g_vv);
    GETH(vvT, g_vvT);    GETH(at, g_at);      GETH(cx, g_cx);
#undef GETH

    float* attn = ((size_t)out_size >= OUT_ELEMS + ATTN_ELEMS) ? (out + OUT_ELEMS) : pATT;

    // Not stream ops; deterministic on every call (no static guards allowed).
    cudaFuncSetAttribute(gemmTC<TFOLD>, cudaFuncAttributeMaxDynamicSharedMemorySize, SMEMDYN);
    cudaFuncSetAttribute(gemmTC<TQQ>,   cudaFuncAttributeMaxDynamicSharedMemorySize, SMEMDYN);
    cudaFuncSetAttribute(gemmTC<TKK>,   cudaFuncAttributeMaxDynamicSharedMemorySize, SMEMDYN);
    cudaFuncSetAttribute(gemmTC<TVV>,   cudaFuncAttributeMaxDynamicSharedMemorySize, SMEMDYN);
    cudaFuncSetAttribute(gemmTC<TSC>,   cudaFuncAttributeMaxDynamicSharedMemorySize, SMEMDYN);
    cudaFuncSetAttribute(gemmTC<TCTX>,  cudaFuncAttributeMaxDynamicSharedMemorySize, SMEMDYN);
    cudaFuncSetAttribute(gemmTC<TTANH>, cudaFuncAttributeMaxDynamicSharedMemorySize, SMEMDYN);

    dim3 T(256);
    // precompute + fp16 converts
    prep1<<<1, 256>>>(cw, cb, Wloc);
    prep2<<<18, 256>>>(swq, sbq, swk, sbk, swv, sbv, bias, bq);
    cvtKn<<<8192, 256>>>((const float4*)query, (__half2*)qh, 2097152);
    cvtKn<<<8192, 256>>>((const float4*)value, (__half2*)vh, 2097152);
    cvtKn<<<1024, 256>>>((const float4*)Wq, (__half2*)Wqh, 262144);
    cvtKn<<<1024, 256>>>((const float4*)Wv, (__half2*)Wvh, 262144);
    cvtT<<<dim3(8, 8), 256>>>(swq, sqT, 256, 256);
    cvtT<<<dim3(8, 8), 256>>>(swk, skT, 256, 256);
    cvtT<<<dim3(8, 8), 256>>>(swv, svT, 256, 256);
    cvtT<<<dim3(32, 64), 256>>>(Wout, WoT, 2048, 1024);

    // weight folds (per head z): Wx2T[d'][e]
    gemmTC<TFOLD><<<dim3(8, 2, 4), T, SMEMDYN>>>(sqT, 0, Wqh,
        Wq2T, 0, 256, 256, 1024, 1024, 0, 0, 0, 0);
    gemmTC<TFOLD><<<dim3(8, 2, 4), T, SMEMDYN>>>(skT, 0, Wvh,
        WvkT, 0, 256, 256, 1024, 1024, 0, 0, 0, 0);
    gemmTC<TFOLD><<<dim3(8, 2, 4), T, SMEMDYN>>>(svT, 0, Wvh,
        WvvT, 0, 256, 256, 1024, 1024, 0, 0, 0, 0);

    // qq / kk / vv: 8192 x 1024, K=1024, fused epilogues emit fp16
    gemmTC<TQQ><<<dim3(8, 64, 1), T, SMEMDYN>>>(qh, 0, Wq2T,
        qq, 0, 1024, 1024, 1024, 1024, pBq2, 0, 0, 0);
    gemmTC<TKK><<<dim3(8, 64, 1), T, SMEMDYN>>>(vh, 0, WvkT,
        kk, 0, 1024, 1024, 1024, 1024, 0, pa, pW2k, pCk);
    gemmTC<TVV><<<dim3(8, 64, 1), T, SMEMDYN>>>(vh, 0, WvvT,
        vv, 0, 1024, 1024, 1024, 1024, 0, pa, pW2v, pCv);
    transVV<<<dim3(16, 8, 64), 256>>>(vv, vvT);

    // attention
    gemmTC<TSC><<<dim3(4, 4, 64), T, SMEMDYN>>>(qq, 0, kk,
        0, attn, 256, 1024, 1024, 512, 0, 0, 0, 0);
    softmax512<<<64 * 512, 128>>>(attn, (__half2*)at);
    gemmTC<TCTX><<<dim3(2, 4, 64), T, SMEMDYN>>>(at, 0, vvT,
        cx, 0, 512, 512, 512, 1024, 0, 0, 0, 0);

    // out = tanh([ctx, query] @ Wout + bout)
    gemmTC<TTANH><<<dim3(8, 64, 1), T, SMEMDYN>>>(cx, qh, WoT,
        0, out, 2048, 1024, 2048, 1024, bout, 0, 0, 0);
}